// round 6
// baseline (speedup 1.0000x reference)
#include <cuda_runtime.h>
#include <cuda_bf16.h>
#include <cstdint>
#include <cstddef>

// B=1024, F=512, N=8 — all heavy math on HMMA bf16 with 3-term split.
// Split operands stored DEDUPED as [hi|lo] (2/3 K); the GEMM loop remaps chunk
// indices to realize the logical [hi|lo|hi] (A) x [hi|hi|lo] (B) pairing.

#define LDK 40   // smem row stride in halves (80B, conflict-free ldmatrix)

// ---------------- static scratch (deduped splits) ----------------
__device__ unsigned short g_xcat3[(size_t)1024 * 2048];   // A-split of [vx|ax]
__device__ unsigned short g_W13[(size_t)4096 * 2048];     // B-split of W1
__device__ unsigned short g_h3[(size_t)8 * 1024 * 1024];  // [z][b][hi512|lo512]
__device__ unsigned short g_W23[(size_t)4096 * 1024];     // B-split of W2
__device__ float g_vaT[1024 * 8 * 512];                   // [B][i][F]
__device__ unsigned short g_X3[(size_t)8192 * 3072];      // conv A split (di-shifted)
__device__ unsigned short g_W3[(size_t)1536 * 3072];      // conv B split
__device__ float g_Y[(size_t)8192 * 1536];                // conv out
__device__ unsigned short g_p3[(size_t)1024 * 4096];      // pooled split
__device__ unsigned short g_A23[(size_t)512 * 4096];      // conv2-collapsed split

// ---------------- helpers ----------------
union Pack8 { unsigned short s[8]; uint4 v; };
__device__ __forceinline__ void split_hi_lo(float x, unsigned short& hi, unsigned short& lo) {
    __nv_bfloat16 h = __float2bfloat16(x);
    float hf = __bfloat162float(h);
    __nv_bfloat16 l = __float2bfloat16(x - hf);
    hi = __bfloat16_as_ushort(h);
    lo = __bfloat16_as_ushort(l);
}
__device__ __forceinline__ uint32_t smem_u32(const void* p) {
    uint32_t a;
    asm("{ .reg .u64 t; cvta.to.shared.u64 t, %1; cvt.u32.u64 %0, t; }" : "=r"(a) : "l"(p));
    return a;
}
__device__ __forceinline__ void ldmatrix_x4(uint32_t& r0, uint32_t& r1, uint32_t& r2, uint32_t& r3,
                                            uint32_t addr) {
    asm volatile("ldmatrix.sync.aligned.m8n8.x4.shared.b16 {%0,%1,%2,%3}, [%4];"
                 : "=r"(r0), "=r"(r1), "=r"(r2), "=r"(r3) : "r"(addr));
}
__device__ __forceinline__ void mma_16816(float* c, const uint32_t* a, const uint32_t* b) {
    asm volatile("mma.sync.aligned.m16n8k16.row.col.f32.bf16.bf16.f32 "
                 "{%0,%1,%2,%3}, {%4,%5,%6,%7}, {%8,%9}, {%0,%1,%2,%3};"
                 : "+f"(c[0]), "+f"(c[1]), "+f"(c[2]), "+f"(c[3])
                 : "r"(a[0]), "r"(a[1]), "r"(a[2]), "r"(a[3]), "r"(b[0]), "r"(b[1]));
}
__device__ __forceinline__ void cp_async16(uint32_t dst, const void* src) {
    asm volatile("cp.async.cg.shared.global [%0], [%1], 16;" :: "r"(dst), "l"(src));
}
#define CP_COMMIT() asm volatile("cp.async.commit_group;" ::: "memory")
#define CP_WAIT0()  asm volatile("cp.async.wait_group 0;" ::: "memory")

// ---------------- operand builders ----------------
// [vx|ax] concat -> A-split [hi|lo], row stride 2048
__global__ void concat_split_kernel(const float* __restrict__ vx, const float* __restrict__ ax) {
    int idx = blockIdx.x * blockDim.x + threadIdx.x;  // 1024*128
    int kv = idx & 127, b = idx >> 7;
    const float* src = (kv < 64) ? (vx + (size_t)b * 512 + kv * 8)
                                 : (ax + (size_t)b * 512 + (kv - 64) * 8);
    float4 x0 = *(const float4*)src, x1 = *(const float4*)(src + 4);
    float vals[8] = {x0.x, x0.y, x0.z, x0.w, x1.x, x1.y, x1.z, x1.w};
    Pack8 hi, lo;
    #pragma unroll
    for (int j = 0; j < 8; j++) split_hi_lo(vals[j], hi.s[j], lo.s[j]);
    size_t e0 = (size_t)b * 2048 + kv * 8;
    *(uint4*)(g_xcat3 + e0)        = hi.v;
    *(uint4*)(g_xcat3 + e0 + 1024) = lo.v;
}

// B-split [hi|lo], row stride 2K
__global__ void split3B_kernel(const float* __restrict__ src, unsigned short* __restrict__ dst,
                               int Kv /* K/8 */, int K) {
    int idx = blockIdx.x * blockDim.x + threadIdx.x;  // R*Kv
    int kv = idx % Kv, r = idx / Kv;
    const float* s = src + (size_t)r * K + kv * 8;
    float4 x0 = *(const float4*)s, x1 = *(const float4*)(s + 4);
    float vals[8] = {x0.x, x0.y, x0.z, x0.w, x1.x, x1.y, x1.z, x1.w};
    Pack8 hi, lo;
    #pragma unroll
    for (int j = 0; j < 8; j++) split_hi_lo(vals[j], hi.s[j], lo.s[j]);
    size_t e0 = (size_t)r * 2 * K + kv * 8;
    *(uint4*)(dst + e0)     = hi.v;
    *(uint4*)(dst + e0 + K) = lo.v;
}

// conv2+mean collapse -> split, row stride 4096
__global__ void pre_A2_kernel(const float* __restrict__ w2) {
    int idx = blockIdx.x * blockDim.x + threadIdx.x;  // 512*512*4
    int q = idx & 3;
    int cf = idx >> 2;
    int f = cf & 511;
    int c = cf >> 9;
    int ip = q >> 1, jp = q & 1;
    const float* wb = w2 + (size_t)(c * 512 + f) * 9;
    float s = 0.f;
    #pragma unroll
    for (int i = 0; i < 2; i++)
        #pragma unroll
        for (int j = 0; j < 2; j++)
            s += wb[(ip - i + 1) * 3 + (jp - j + 1)];
    unsigned short hi, lo;
    split_hi_lo(0.25f * s, hi, lo);
    size_t e0 = (size_t)c * 4096 + f * 4 + q;
    g_A23[e0]        = hi;
    g_A23[e0 + 2048] = lo;
}

// conv A operand split: X3[r=(b,i)][di*512 + f], [hi|lo], row stride 3072
__global__ void build_x3_kernel() {
    int idx = blockIdx.x * blockDim.x + threadIdx.x;   // 8192*3*64
    int fg = idx & 63;
    int di = (idx >> 6) % 3;
    int r  = idx / 192;
    int b = r >> 3, i = r & 7;
    int src = i + di - 1;
    float vals[8];
    if (src >= 0 && src < 8) {
        const float4* p = (const float4*)(g_vaT + ((size_t)(b * 8 + src) * 512) + fg * 8);
        float4 x0 = p[0], x1 = p[1];
        vals[0] = x0.x; vals[1] = x0.y; vals[2] = x0.z; vals[3] = x0.w;
        vals[4] = x1.x; vals[5] = x1.y; vals[6] = x1.z; vals[7] = x1.w;
    } else {
        #pragma unroll
        for (int j = 0; j < 8; j++) vals[j] = 0.f;
    }
    Pack8 hi, lo;
    #pragma unroll
    for (int j = 0; j < 8; j++) split_hi_lo(vals[j], hi.s[j], lo.s[j]);
    size_t e0 = (size_t)r * 3072 + di * 512 + fg * 8;
    *(uint4*)(g_X3 + e0)        = hi.v;
    *(uint4*)(g_X3 + e0 + 1536) = lo.v;
}

// conv B operand split: W3[n=t*512+c][di*512+f], [hi|lo], row stride 3072
__global__ void build_w3_kernel(const float* __restrict__ c1w) {
    int idx = blockIdx.x * blockDim.x + threadIdx.x;   // 1536*3*64
    int fg = idx & 63;
    int di = (idx >> 6) % 3;
    int n  = idx / 192;
    int t = n >> 9, c = n & 511;
    Pack8 hi, lo;
    #pragma unroll
    for (int j = 0; j < 8; j++) {
        int f = fg * 8 + j;
        size_t base = ((size_t)(c * 512 + f) * 3 + di) * 3;
        float w;
        if (t == 0)      w = c1w[base] + c1w[base + 1] + c1w[base + 2];
        else if (t == 1) w = c1w[base];
        else             w = c1w[base + 2];
        split_hi_lo(w, hi.s[j], lo.s[j]);
    }
    size_t e0 = (size_t)n * 3072 + di * 512 + fg * 8;
    *(uint4*)(g_W3 + e0)        = hi.v;
    *(uint4*)(g_W3 + e0 + 1536) = lo.v;
}

// ---------------- unified HMMA GEMM ----------------
// Logical K = Ks (3-term); stored K = 2Ks/3, deduped [hi|lo].
// A logical blocks [hi|lo|hi]: kA = it<2nb ? it : it-2nb
// B logical blocks [hi|hi|lo]: kB = it<nb  ? it : it-nb      (nb = NIT/3)
// MODE 0: outF = acc (conv->Y)   MODE 1: relu(acc+bias) (G3->out)
// MODE 2: h3 deduped split store (G1)   MODE 3: vaT epilogue (G2)
template <int TM, int MODE>
__global__ void __launch_bounds__((TM == 256) ? 512 : 256, 2)
hmma_kernel(const unsigned short* __restrict__ A, const unsigned short* __restrict__ Bm,
            const float* __restrict__ bias, float* __restrict__ outF,
            unsigned short* __restrict__ outH, const float* __restrict__ vx,
            int Ks, int ldc, size_t batchA, size_t batchB, int batchBias)
{
    constexpr int THREADS = (TM == 256) ? 512 : 256;
    constexpr int ROWS = TM + 128;
    constexpr int CH = ROWS * 4 / THREADS;
    constexpr int WMC = TM / 64;
    constexpr int ABUF = TM * LDK;
    constexpr int BBUF = 128 * LDK;

    extern __shared__ __align__(16) unsigned short smem[];
    unsigned short* sA = smem;                 // [2][ABUF]
    unsigned short* sB = smem + 2 * ABUF;      // [2][BBUF]

    const int tid = threadIdx.x;
    const int wid = tid >> 5, lane = tid & 31;
    const int m0 = blockIdx.y * TM;
    const int n0 = blockIdx.x * 128;
    const int z  = blockIdx.z;
    const int wm = (wid % WMC) * 64;
    const int wn = (wid / WMC) * 32;

    const int SK = (2 * Ks) / 3;        // stored row length
    const int NIT = Ks / 32;
    const int nb = NIT / 3;

    A  += (size_t)z * batchA;
    Bm += (size_t)z * batchB;
    if (MODE >= 1) bias += (size_t)z * batchBias;

    // staging maps (cp.async)
    const unsigned short* gp[CH];
    uint32_t sdA[CH];
    bool isA_[CH];
    #pragma unroll
    for (int t = 0; t < CH; t++) {
        int id = tid + t * THREADS;
        int r = id >> 2, q = id & 3;
        if (r < TM) {
            gp[t] = A + (size_t)(m0 + r) * SK + q * 8;
            sdA[t] = smem_u32(sA + r * LDK + q * 8);
            isA_[t] = true;
        } else {
            gp[t] = Bm + (size_t)(n0 + r - TM) * SK + q * 8;
            sdA[t] = smem_u32(sB + (r - TM) * LDK + q * 8);
            isA_[t] = false;
        }
    }

    float acc[4][4][4];
    #pragma unroll
    for (int i = 0; i < 4; i++)
        #pragma unroll
        for (int j = 0; j < 4; j++)
            #pragma unroll
            for (int q = 0; q < 4; q++) acc[i][j][q] = 0.f;

    const uint32_t sA_base = smem_u32(sA);
    const uint32_t sB_base = smem_u32(sB);
    const int aRow = wm + (lane & 15);
    const int aKof = (lane >> 4) * 8;
    const int bRow = wn + ((lane & 7) | ((lane >> 4) << 3));
    const int bKof = ((lane >> 3) & 1) * 8;

    // stage chunk k into buffer buf
    auto stage = [&](int k, int buf) {
        int kA = (k < 2 * nb) ? k : k - 2 * nb;
        int kB = (k < nb) ? k : k - nb;
        #pragma unroll
        for (int t = 0; t < CH; t++) {
            const unsigned short* src = gp[t] + (size_t)(isA_[t] ? kA : kB) * 32;
            uint32_t dst = sdA[t] + (uint32_t)buf * (isA_[t] ? ABUF : BBUF) * 2;
            cp_async16(dst, src);
        }
        CP_COMMIT();
    };

    stage(0, 0);
    CP_WAIT0();
    __syncthreads();

    for (int it = 0; it < NIT; it++) {
        const int cur = it & 1;
        const bool more = (it + 1) < NIT;
        if (more) stage(it + 1, cur ^ 1);

        const uint32_t aBuf = sA_base + cur * (ABUF * 2);
        const uint32_t bBuf = sB_base + cur * (BBUF * 2);
        #pragma unroll
        for (int ks = 0; ks < 32; ks += 16) {
            uint32_t af[4][4], bf[4][2];
            #pragma unroll
            for (int mt = 0; mt < 4; mt++)
                ldmatrix_x4(af[mt][0], af[mt][1], af[mt][2], af[mt][3],
                            aBuf + (uint32_t)(((aRow + mt * 16) * LDK + ks + aKof) * 2));
            #pragma unroll
            for (int np = 0; np < 2; np++)
                ldmatrix_x4(bf[np * 2][0], bf[np * 2][1], bf[np * 2 + 1][0], bf[np * 2 + 1][1],
                            bBuf + (uint32_t)(((bRow + np * 16) * LDK + ks + bKof) * 2));
            #pragma unroll
            for (int mt = 0; mt < 4; mt++)
                #pragma unroll
                for (int nt = 0; nt < 4; nt++)
                    mma_16816(acc[mt][nt], af[mt], bf[nt]);
        }
        if (more) CP_WAIT0();
        __syncthreads();
    }

    // epilogue
    const int erow = lane >> 2;
    const int ecol = (lane & 3) * 2;
    #pragma unroll
    for (int mt = 0; mt < 4; mt++) {
        #pragma unroll
        for (int nt = 0; nt < 4; nt++) {
            const int r0 = m0 + wm + mt * 16 + erow;
            const int c  = n0 + wn + nt * 8 + ecol;
            const float* v = acc[mt][nt];
            if (MODE == 0) {
                *(float2*)&outF[(size_t)r0 * ldc + c] = make_float2(v[0], v[1]);
                *(float2*)&outF[(size_t)(r0 + 8) * ldc + c] = make_float2(v[2], v[3]);
            } else if (MODE == 1) {
                float b0 = bias[c], b1 = bias[c + 1];
                *(float2*)&outF[(size_t)r0 * ldc + c] =
                    make_float2(fmaxf(v[0] + b0, 0.f), fmaxf(v[1] + b1, 0.f));
                *(float2*)&outF[(size_t)(r0 + 8) * ldc + c] =
                    make_float2(fmaxf(v[2] + b0, 0.f), fmaxf(v[3] + b1, 0.f));
            } else if (MODE == 2) {
                float b0 = bias[c], b1 = bias[c + 1];
                int zz = c >> 9, f = c & 511;
                #pragma unroll
                for (int hr = 0; hr < 2; hr++) {
                    float y0 = fmaxf(v[hr * 2] + b0, 0.f);
                    float y1 = fmaxf(v[hr * 2 + 1] + b1, 0.f);
                    unsigned short h0, l0, h1, l1;
                    split_hi_lo(y0, h0, l0);
                    split_hi_lo(y1, h1, l1);
                    uint32_t hip = (uint32_t)h0 | ((uint32_t)h1 << 16);
                    uint32_t lop = (uint32_t)l0 | ((uint32_t)l1 << 16);
                    size_t base = ((size_t)zz * 1024 + (r0 + hr * 8)) * 1024 + f;
                    *(uint32_t*)&outH[base]       = hip;
                    *(uint32_t*)&outH[base + 512] = lop;
                }
            } else {  // MODE 3
                float b0 = bias[c], b1 = bias[c + 1];
                #pragma unroll
                for (int hr = 0; hr < 2; hr++) {
                    int r = r0 + hr * 8;
                    float s0 = vx[(size_t)r * 512 + c];
                    float s1 = vx[(size_t)r * 512 + c + 1];
                    float y0 = s0 * fmaxf(v[hr * 2] + b0, 0.f);
                    float y1 = s1 * fmaxf(v[hr * 2 + 1] + b1, 0.f);
                    *(float2*)&outF[((size_t)r * 8 + z) * 512 + c] = make_float2(y0, y1);
                }
            }
        }
    }
}

// ---------------- pool: Y -> p3 (deduped split) ----------------
__global__ void pool_split_kernel(const float* __restrict__ Y, const float* __restrict__ c1b) {
    int idx = blockIdx.x * blockDim.x + threadIdx.x;   // 1024*512
    int c = idx & 511, b = idx >> 9;
    float bias = c1b[c];
    float m00 = -1e30f, m01 = -1e30f, m10 = -1e30f, m11 = -1e30f;
    #pragma unroll
    for (int i = 0; i < 8; i++) {
        size_t base = (size_t)(b * 8 + i) * 1536;
        float yM = Y[base + c];
        float yB = Y[base + 512 + c];
        float yC = Y[base + 1024 + c];
        float vL = fmaxf(yM - yB, yM);
        float vR = fmaxf(yM - yC, yM);
        if (i < 4) { m00 = fmaxf(m00, vL); m01 = fmaxf(m01, vR); }
        else       { m10 = fmaxf(m10, vL); m11 = fmaxf(m11, vR); }
    }
    float p[4] = {m00 + bias, m01 + bias, m10 + bias, m11 + bias};
    ushort4 hi, lo;
    split_hi_lo(p[0], hi.x, lo.x);
    split_hi_lo(p[1], hi.y, lo.y);
    split_hi_lo(p[2], hi.z, lo.z);
    split_hi_lo(p[3], hi.w, lo.w);
    size_t e0 = (size_t)b * 4096 + c * 4;
    *(ushort4*)(g_p3 + e0)        = hi;
    *(ushort4*)(g_p3 + e0 + 2048) = lo;
}

// ---------------- launch ----------------
extern "C" void kernel_launch(void* const* d_in, const int* in_sizes, int n_in,
                              void* d_out, int out_size) {
    (void)in_sizes; (void)n_in; (void)out_size;
    const float* vx  = (const float*)d_in[0];
    const float* ax  = (const float*)d_in[1];
    const float* W1  = (const float*)d_in[2];
    const float* b1  = (const float*)d_in[3];
    const float* W2  = (const float*)d_in[4];
    const float* b2  = (const float*)d_in[5];
    const float* c1w = (const float*)d_in[6];
    const float* c1b = (const float*)d_in[7];
    const float* c2w = (const float*)d_in[8];
    const float* c2b = (const float*)d_in[9];
    float* out = (float*)d_out;

    void *p_xcat3, *p_W13, *p_h3, *p_W23, *p_X3, *p_W3, *p_Y, *p_p3, *p_A23, *p_vaT;
    cudaGetSymbolAddress(&p_xcat3, g_xcat3);
    cudaGetSymbolAddress(&p_W13,   g_W13);
    cudaGetSymbolAddress(&p_h3,    g_h3);
    cudaGetSymbolAddress(&p_W23,   g_W23);
    cudaGetSymbolAddress(&p_X3,    g_X3);
    cudaGetSymbolAddress(&p_W3,    g_W3);
    cudaGetSymbolAddress(&p_Y,     g_Y);
    cudaGetSymbolAddress(&p_p3,    g_p3);
    cudaGetSymbolAddress(&p_A23,   g_A23);
    cudaGetSymbolAddress(&p_vaT,   g_vaT);

    const int SM256 = (2 * 256 + 2 * 128) * LDK * 2;  // 61440
    const int SM128 = (2 * 128 + 2 * 128) * LDK * 2;  // 40960
    cudaFuncSetAttribute(hmma_kernel<256, 0>, cudaFuncAttributeMaxDynamicSharedMemorySize, SM256);
    cudaFuncSetAttribute(hmma_kernel<256, 2>, cudaFuncAttributeMaxDynamicSharedMemorySize, SM256);
    cudaFuncSetAttribute(hmma_kernel<256, 3>, cudaFuncAttributeMaxDynamicSharedMemorySize, SM256);
    cudaFuncSetAttribute(hmma_kernel<128, 1>, cudaFuncAttributeMaxDynamicSharedMemorySize, SM128);

    // operand builders
    concat_split_kernel<<<512, 256>>>(vx, ax);                              // xcat3
    split3B_kernel<<<2048, 256>>>(W1, (unsigned short*)p_W13, 128, 1024);   // W1 split
    split3B_kernel<<<1024, 256>>>(W2, (unsigned short*)p_W23, 64, 512);     // W2 split
    pre_A2_kernel<<<4096, 256>>>(c2w);                                      // A2 split
    build_w3_kernel<<<1152, 256>>>(c1w);                                    // W3 split

    // GEMM1: h3 = split(relu(xcat*W1^T + b1)); logical K=3072
    hmma_kernel<256, 2><<<dim3(32, 4), 512, SM256>>>(
        (const unsigned short*)p_xcat3, (const unsigned short*)p_W13, b1,
        nullptr, (unsigned short*)p_h3, nullptr, 3072, 0, 0, 0, 0);

    // GEMM2 (batch z): vaT = vx*relu(h_z*W2_z^T + b2_z); logical K=1536
    hmma_kernel<256, 3><<<dim3(4, 4, 8), 512, SM256>>>(
        (const unsigned short*)p_h3, (const unsigned short*)p_W23, b2,
        (float*)p_vaT, nullptr, vx, 1536, 0,
        (size_t)1024 * 1024, (size_t)512 * 1024, 512);

    // conv operand, then conv GEMM: Y = X3*W3^T; logical K=4608
    build_x3_kernel<<<6144, 256>>>();
    hmma_kernel<256, 0><<<dim3(12, 32), 512, SM256>>>(
        (const unsigned short*)p_X3, (const unsigned short*)p_W3, nullptr,
        (float*)p_Y, nullptr, nullptr, 4608, 1536, 0, 0, 0);

    // pool -> p3
    pool_split_kernel<<<2048, 256>>>((const float*)p_Y, c1b);

    // GEMM3: out = relu(p*A2^T + c2b); logical K=6144
    hmma_kernel<128, 1><<<dim3(4, 8), 256, SM128>>>(
        (const unsigned short*)p_p3, (const unsigned short*)p_A23, c2b,
        out, nullptr, nullptr, 6144, 512, 0, 0, 0);
}

// round 7
// speedup vs baseline: 4.4999x; 4.4999x over previous
#include <cuda_runtime.h>
#include <cuda_bf16.h>
#include <cstdint>
#include <cstddef>

// B=1024, F=512, N=8 — all heavy math on HMMA bf16 with 3-term split.
// Split operands stored DEDUPED as [hi|lo] (2/3 K); the GEMM loop remaps chunk
// indices to realize the logical [hi|lo|hi] (A) x [hi|hi|lo] (B) pairing.

#define LDK 40   // smem row stride in halves (80B, conflict-free ldmatrix)

// ---------------- static scratch (deduped splits) ----------------
__device__ unsigned short g_xcat3[(size_t)1024 * 2048];   // A-split of [vx|ax]
__device__ unsigned short g_W13[(size_t)4096 * 2048];     // B-split of W1
__device__ unsigned short g_h3[(size_t)8 * 1024 * 1024];  // [z][b][hi512|lo512]
__device__ unsigned short g_W23[(size_t)4096 * 1024];     // B-split of W2
__device__ float g_vaT[1024 * 8 * 512];                   // [B][i][F]
__device__ unsigned short g_X3[(size_t)8192 * 3072];      // conv A split (di-shifted)
__device__ unsigned short g_W3[(size_t)1536 * 3072];      // conv B split
__device__ float g_Y[(size_t)8192 * 1536];                // conv out
__device__ unsigned short g_p3[(size_t)1024 * 4096];      // pooled split
__device__ unsigned short g_A23[(size_t)512 * 4096];      // conv2-collapsed split

// ---------------- helpers ----------------
union Pack8 { unsigned short s[8]; uint4 v; };
__device__ __forceinline__ void split_hi_lo(float x, unsigned short& hi, unsigned short& lo) {
    __nv_bfloat16 h = __float2bfloat16(x);
    float hf = __bfloat162float(h);
    __nv_bfloat16 l = __float2bfloat16(x - hf);
    hi = __bfloat16_as_ushort(h);
    lo = __bfloat16_as_ushort(l);
}
__device__ __forceinline__ uint32_t smem_u32(const void* p) {
    uint32_t a;
    asm("{ .reg .u64 t; cvta.to.shared.u64 t, %1; cvt.u32.u64 %0, t; }" : "=r"(a) : "l"(p));
    return a;
}
__device__ __forceinline__ void ldmatrix_x4(uint32_t& r0, uint32_t& r1, uint32_t& r2, uint32_t& r3,
                                            uint32_t addr) {
    asm volatile("ldmatrix.sync.aligned.m8n8.x4.shared.b16 {%0,%1,%2,%3}, [%4];"
                 : "=r"(r0), "=r"(r1), "=r"(r2), "=r"(r3) : "r"(addr));
}
__device__ __forceinline__ void mma_16816(float* c, const uint32_t* a, const uint32_t* b) {
    asm volatile("mma.sync.aligned.m16n8k16.row.col.f32.bf16.bf16.f32 "
                 "{%0,%1,%2,%3}, {%4,%5,%6,%7}, {%8,%9}, {%0,%1,%2,%3};"
                 : "+f"(c[0]), "+f"(c[1]), "+f"(c[2]), "+f"(c[3])
                 : "r"(a[0]), "r"(a[1]), "r"(a[2]), "r"(a[3]), "r"(b[0]), "r"(b[1]));
}
__device__ __forceinline__ void cp_async16(uint32_t dst, const void* src) {
    asm volatile("cp.async.cg.shared.global [%0], [%1], 16;" :: "r"(dst), "l"(src));
}
#define CP_COMMIT() asm volatile("cp.async.commit_group;" ::: "memory")
#define CP_WAIT0()  asm volatile("cp.async.wait_group 0;" ::: "memory")

// ---------------- operand builders ----------------
// [vx|ax] concat -> A-split [hi|lo], row stride 2048
__global__ void concat_split_kernel(const float* __restrict__ vx, const float* __restrict__ ax) {
    int idx = blockIdx.x * blockDim.x + threadIdx.x;  // 1024*128
    int kv = idx & 127, b = idx >> 7;
    const float* src = (kv < 64) ? (vx + (size_t)b * 512 + kv * 8)
                                 : (ax + (size_t)b * 512 + (kv - 64) * 8);
    float4 x0 = *(const float4*)src, x1 = *(const float4*)(src + 4);
    float vals[8] = {x0.x, x0.y, x0.z, x0.w, x1.x, x1.y, x1.z, x1.w};
    Pack8 hi, lo;
    #pragma unroll
    for (int j = 0; j < 8; j++) split_hi_lo(vals[j], hi.s[j], lo.s[j]);
    size_t e0 = (size_t)b * 2048 + kv * 8;
    *(uint4*)(g_xcat3 + e0)        = hi.v;
    *(uint4*)(g_xcat3 + e0 + 1024) = lo.v;
}

// B-split [hi|lo], row stride 2K
__global__ void split3B_kernel(const float* __restrict__ src, unsigned short* __restrict__ dst,
                               int Kv /* K/8 */, int K) {
    int idx = blockIdx.x * blockDim.x + threadIdx.x;  // R*Kv
    int kv = idx % Kv, r = idx / Kv;
    const float* s = src + (size_t)r * K + kv * 8;
    float4 x0 = *(const float4*)s, x1 = *(const float4*)(s + 4);
    float vals[8] = {x0.x, x0.y, x0.z, x0.w, x1.x, x1.y, x1.z, x1.w};
    Pack8 hi, lo;
    #pragma unroll
    for (int j = 0; j < 8; j++) split_hi_lo(vals[j], hi.s[j], lo.s[j]);
    size_t e0 = (size_t)r * 2 * K + kv * 8;
    *(uint4*)(dst + e0)     = hi.v;
    *(uint4*)(dst + e0 + K) = lo.v;
}

// conv2+mean collapse -> split, row stride 4096
__global__ void pre_A2_kernel(const float* __restrict__ w2) {
    int idx = blockIdx.x * blockDim.x + threadIdx.x;  // 512*512*4
    int q = idx & 3;
    int cf = idx >> 2;
    int f = cf & 511;
    int c = cf >> 9;
    int ip = q >> 1, jp = q & 1;
    const float* wb = w2 + (size_t)(c * 512 + f) * 9;
    float s = 0.f;
    #pragma unroll
    for (int i = 0; i < 2; i++)
        #pragma unroll
        for (int j = 0; j < 2; j++)
            s += wb[(ip - i + 1) * 3 + (jp - j + 1)];
    unsigned short hi, lo;
    split_hi_lo(0.25f * s, hi, lo);
    size_t e0 = (size_t)c * 4096 + f * 4 + q;
    g_A23[e0]        = hi;
    g_A23[e0 + 2048] = lo;
}

// conv A operand split: X3[r=(b,i)][di*512 + f], [hi|lo], row stride 3072
__global__ void build_x3_kernel() {
    int idx = blockIdx.x * blockDim.x + threadIdx.x;   // 8192*3*64
    int fg = idx & 63;
    int di = (idx >> 6) % 3;
    int r  = idx / 192;
    int b = r >> 3, i = r & 7;
    int src = i + di - 1;
    float vals[8];
    if (src >= 0 && src < 8) {
        const float4* p = (const float4*)(g_vaT + ((size_t)(b * 8 + src) * 512) + fg * 8);
        float4 x0 = p[0], x1 = p[1];
        vals[0] = x0.x; vals[1] = x0.y; vals[2] = x0.z; vals[3] = x0.w;
        vals[4] = x1.x; vals[5] = x1.y; vals[6] = x1.z; vals[7] = x1.w;
    } else {
        #pragma unroll
        for (int j = 0; j < 8; j++) vals[j] = 0.f;
    }
    Pack8 hi, lo;
    #pragma unroll
    for (int j = 0; j < 8; j++) split_hi_lo(vals[j], hi.s[j], lo.s[j]);
    size_t e0 = (size_t)r * 3072 + di * 512 + fg * 8;
    *(uint4*)(g_X3 + e0)        = hi.v;
    *(uint4*)(g_X3 + e0 + 1536) = lo.v;
}

// conv B operand split: W3[n=t*512+c][di*512+f], [hi|lo], row stride 3072
__global__ void build_w3_kernel(const float* __restrict__ c1w) {
    int idx = blockIdx.x * blockDim.x + threadIdx.x;   // 1536*3*64
    int fg = idx & 63;
    int di = (idx >> 6) % 3;
    int n  = idx / 192;
    int t = n >> 9, c = n & 511;
    Pack8 hi, lo;
    #pragma unroll
    for (int j = 0; j < 8; j++) {
        int f = fg * 8 + j;
        size_t base = ((size_t)(c * 512 + f) * 3 + di) * 3;
        float w;
        if (t == 0)      w = c1w[base] + c1w[base + 1] + c1w[base + 2];
        else if (t == 1) w = c1w[base];
        else             w = c1w[base + 2];
        split_hi_lo(w, hi.s[j], lo.s[j]);
    }
    size_t e0 = (size_t)n * 3072 + di * 512 + fg * 8;
    *(uint4*)(g_W3 + e0)        = hi.v;
    *(uint4*)(g_W3 + e0 + 1536) = lo.v;
}

// ---------------- unified HMMA GEMM ----------------
// Logical K = Ks (3-term); stored K = 2Ks/3, deduped [hi|lo].
// A logical blocks [hi|lo|hi]: kA = it<2nb ? it : it-2nb
// B logical blocks [hi|hi|lo]: kB = it<nb  ? it : it-nb      (nb = NIT/3)
// MODE 0: outF = acc (conv->Y)   MODE 1: relu(acc+bias) (G3->out)
// MODE 2: h3 deduped split store (G1)   MODE 3: vaT epilogue (G2)
template <int TM, int MODE>
__global__ void __launch_bounds__((TM == 256) ? 512 : 256, (TM == 256) ? 1 : 2)
hmma_kernel(const unsigned short* __restrict__ A, const unsigned short* __restrict__ Bm,
            const float* __restrict__ bias, float* __restrict__ outF,
            unsigned short* __restrict__ outH, const float* __restrict__ vx,
            int Ks, int ldc, size_t batchA, size_t batchB, int batchBias)
{
    constexpr int THREADS = (TM == 256) ? 512 : 256;
    constexpr int ROWS = TM + 128;
    constexpr int CH = ROWS * 4 / THREADS;
    constexpr int WMC = TM / 64;
    constexpr int ABUF = TM * LDK;
    constexpr int BBUF = 128 * LDK;

    extern __shared__ __align__(16) unsigned short smem[];
    unsigned short* sA = smem;                 // [2][ABUF]
    unsigned short* sB = smem + 2 * ABUF;      // [2][BBUF]

    const int tid = threadIdx.x;
    const int wid = tid >> 5, lane = tid & 31;
    const int m0 = blockIdx.y * TM;
    const int n0 = blockIdx.x * 128;
    const int z  = blockIdx.z;
    const int wm = (wid % WMC) * 64;
    const int wn = (wid / WMC) * 32;

    const int SK = (2 * Ks) / 3;        // stored row length
    const int NIT = Ks / 32;
    const int nb = NIT / 3;

    A  += (size_t)z * batchA;
    Bm += (size_t)z * batchB;
    if (MODE >= 1) bias += (size_t)z * batchBias;

    // staging maps (cp.async)
    const unsigned short* gp[CH];
    uint32_t sdA[CH];
    bool isA_[CH];
    #pragma unroll
    for (int t = 0; t < CH; t++) {
        int id = tid + t * THREADS;
        int r = id >> 2, q = id & 3;
        if (r < TM) {
            gp[t] = A + (size_t)(m0 + r) * SK + q * 8;
            sdA[t] = smem_u32(sA + r * LDK + q * 8);
            isA_[t] = true;
        } else {
            gp[t] = Bm + (size_t)(n0 + r - TM) * SK + q * 8;
            sdA[t] = smem_u32(sB + (r - TM) * LDK + q * 8);
            isA_[t] = false;
        }
    }

    float acc[4][4][4];
    #pragma unroll
    for (int i = 0; i < 4; i++)
        #pragma unroll
        for (int j = 0; j < 4; j++)
            #pragma unroll
            for (int q = 0; q < 4; q++) acc[i][j][q] = 0.f;

    const uint32_t sA_base = smem_u32(sA);
    const uint32_t sB_base = smem_u32(sB);
    const int aRow = wm + (lane & 15);
    const int aKof = (lane >> 4) * 8;
    const int bRow = wn + ((lane & 7) | ((lane >> 4) << 3));
    const int bKof = ((lane >> 3) & 1) * 8;

    // stage chunk k into buffer buf
    auto stage = [&](int k, int buf) {
        int kA = (k < 2 * nb) ? k : k - 2 * nb;
        int kB = (k < nb) ? k : k - nb;
        #pragma unroll
        for (int t = 0; t < CH; t++) {
            const unsigned short* src = gp[t] + (size_t)(isA_[t] ? kA : kB) * 32;
            uint32_t dst = sdA[t] + (uint32_t)buf * (isA_[t] ? ABUF : BBUF) * 2;
            cp_async16(dst, src);
        }
        CP_COMMIT();
    };

    stage(0, 0);
    CP_WAIT0();
    __syncthreads();

    for (int it = 0; it < NIT; it++) {
        const int cur = it & 1;
        const bool more = (it + 1) < NIT;
        if (more) stage(it + 1, cur ^ 1);

        const uint32_t aBuf = sA_base + cur * (ABUF * 2);
        const uint32_t bBuf = sB_base + cur * (BBUF * 2);
        #pragma unroll
        for (int ks = 0; ks < 32; ks += 16) {
            uint32_t af[4][4], bf[4][2];
            #pragma unroll
            for (int mt = 0; mt < 4; mt++)
                ldmatrix_x4(af[mt][0], af[mt][1], af[mt][2], af[mt][3],
                            aBuf + (uint32_t)(((aRow + mt * 16) * LDK + ks + aKof) * 2));
            #pragma unroll
            for (int np = 0; np < 2; np++)
                ldmatrix_x4(bf[np * 2][0], bf[np * 2][1], bf[np * 2 + 1][0], bf[np * 2 + 1][1],
                            bBuf + (uint32_t)(((bRow + np * 16) * LDK + ks + bKof) * 2));
            #pragma unroll
            for (int mt = 0; mt < 4; mt++)
                #pragma unroll
                for (int nt = 0; nt < 4; nt++)
                    mma_16816(acc[mt][nt], af[mt], bf[nt]);
        }
        if (more) CP_WAIT0();
        __syncthreads();
    }

    // epilogue
    const int erow = lane >> 2;
    const int ecol = (lane & 3) * 2;
    #pragma unroll
    for (int mt = 0; mt < 4; mt++) {
        #pragma unroll
        for (int nt = 0; nt < 4; nt++) {
            const int r0 = m0 + wm + mt * 16 + erow;
            const int c  = n0 + wn + nt * 8 + ecol;
            const float* v = acc[mt][nt];
            if (MODE == 0) {
                *(float2*)&outF[(size_t)r0 * ldc + c] = make_float2(v[0], v[1]);
                *(float2*)&outF[(size_t)(r0 + 8) * ldc + c] = make_float2(v[2], v[3]);
            } else if (MODE == 1) {
                float b0 = bias[c], b1 = bias[c + 1];
                *(float2*)&outF[(size_t)r0 * ldc + c] =
                    make_float2(fmaxf(v[0] + b0, 0.f), fmaxf(v[1] + b1, 0.f));
                *(float2*)&outF[(size_t)(r0 + 8) * ldc + c] =
                    make_float2(fmaxf(v[2] + b0, 0.f), fmaxf(v[3] + b1, 0.f));
            } else if (MODE == 2) {
                float b0 = bias[c], b1 = bias[c + 1];
                int zz = c >> 9, f = c & 511;
                #pragma unroll
                for (int hr = 0; hr < 2; hr++) {
                    float y0 = fmaxf(v[hr * 2] + b0, 0.f);
                    float y1 = fmaxf(v[hr * 2 + 1] + b1, 0.f);
                    unsigned short h0, l0, h1, l1;
                    split_hi_lo(y0, h0, l0);
                    split_hi_lo(y1, h1, l1);
                    uint32_t hip = (uint32_t)h0 | ((uint32_t)h1 << 16);
                    uint32_t lop = (uint32_t)l0 | ((uint32_t)l1 << 16);
                    size_t base = ((size_t)zz * 1024 + (r0 + hr * 8)) * 1024 + f;
                    *(uint32_t*)&outH[base]       = hip;
                    *(uint32_t*)&outH[base + 512] = lop;
                }
            } else {  // MODE 3
                float b0 = bias[c], b1 = bias[c + 1];
                #pragma unroll
                for (int hr = 0; hr < 2; hr++) {
                    int r = r0 + hr * 8;
                    float s0 = vx[(size_t)r * 512 + c];
                    float s1 = vx[(size_t)r * 512 + c + 1];
                    float y0 = s0 * fmaxf(v[hr * 2] + b0, 0.f);
                    float y1 = s1 * fmaxf(v[hr * 2 + 1] + b1, 0.f);
                    *(float2*)&outF[((size_t)r * 8 + z) * 512 + c] = make_float2(y0, y1);
                }
            }
        }
    }
}

// ---------------- pool: Y -> p3 (deduped split) ----------------
__global__ void pool_split_kernel(const float* __restrict__ Y, const float* __restrict__ c1b) {
    int idx = blockIdx.x * blockDim.x + threadIdx.x;   // 1024*512
    int c = idx & 511, b = idx >> 9;
    float bias = c1b[c];
    float m00 = -1e30f, m01 = -1e30f, m10 = -1e30f, m11 = -1e30f;
    #pragma unroll
    for (int i = 0; i < 8; i++) {
        size_t base = (size_t)(b * 8 + i) * 1536;
        float yM = Y[base + c];
        float yB = Y[base + 512 + c];
        float yC = Y[base + 1024 + c];
        float vL = fmaxf(yM - yB, yM);
        float vR = fmaxf(yM - yC, yM);
        if (i < 4) { m00 = fmaxf(m00, vL); m01 = fmaxf(m01, vR); }
        else       { m10 = fmaxf(m10, vL); m11 = fmaxf(m11, vR); }
    }
    float p[4] = {m00 + bias, m01 + bias, m10 + bias, m11 + bias};
    ushort4 hi, lo;
    split_hi_lo(p[0], hi.x, lo.x);
    split_hi_lo(p[1], hi.y, lo.y);
    split_hi_lo(p[2], hi.z, lo.z);
    split_hi_lo(p[3], hi.w, lo.w);
    size_t e0 = (size_t)b * 4096 + c * 4;
    *(ushort4*)(g_p3 + e0)        = hi;
    *(ushort4*)(g_p3 + e0 + 2048) = lo;
}

// ---------------- launch ----------------
extern "C" void kernel_launch(void* const* d_in, const int* in_sizes, int n_in,
                              void* d_out, int out_size) {
    (void)in_sizes; (void)n_in; (void)out_size;
    const float* vx  = (const float*)d_in[0];
    const float* ax  = (const float*)d_in[1];
    const float* W1  = (const float*)d_in[2];
    const float* b1  = (const float*)d_in[3];
    const float* W2  = (const float*)d_in[4];
    const float* b2  = (const float*)d_in[5];
    const float* c1w = (const float*)d_in[6];
    const float* c1b = (const float*)d_in[7];
    const float* c2w = (const float*)d_in[8];
    const float* c2b = (const float*)d_in[9];
    float* out = (float*)d_out;

    void *p_xcat3, *p_W13, *p_h3, *p_W23, *p_X3, *p_W3, *p_Y, *p_p3, *p_A23, *p_vaT;
    cudaGetSymbolAddress(&p_xcat3, g_xcat3);
    cudaGetSymbolAddress(&p_W13,   g_W13);
    cudaGetSymbolAddress(&p_h3,    g_h3);
    cudaGetSymbolAddress(&p_W23,   g_W23);
    cudaGetSymbolAddress(&p_X3,    g_X3);
    cudaGetSymbolAddress(&p_W3,    g_W3);
    cudaGetSymbolAddress(&p_Y,     g_Y);
    cudaGetSymbolAddress(&p_p3,    g_p3);
    cudaGetSymbolAddress(&p_A23,   g_A23);
    cudaGetSymbolAddress(&p_vaT,   g_vaT);

    const int SM256 = (2 * 256 + 2 * 128) * LDK * 2;  // 61440
    const int SM128 = (2 * 128 + 2 * 128) * LDK * 2;  // 40960
    cudaFuncSetAttribute(hmma_kernel<256, 0>, cudaFuncAttributeMaxDynamicSharedMemorySize, SM256);
    cudaFuncSetAttribute(hmma_kernel<256, 2>, cudaFuncAttributeMaxDynamicSharedMemorySize, SM256);
    cudaFuncSetAttribute(hmma_kernel<256, 3>, cudaFuncAttributeMaxDynamicSharedMemorySize, SM256);
    cudaFuncSetAttribute(hmma_kernel<128, 1>, cudaFuncAttributeMaxDynamicSharedMemorySize, SM128);

    // operand builders
    concat_split_kernel<<<512, 256>>>(vx, ax);                              // xcat3
    split3B_kernel<<<2048, 256>>>(W1, (unsigned short*)p_W13, 128, 1024);   // W1 split
    split3B_kernel<<<1024, 256>>>(W2, (unsigned short*)p_W23, 64, 512);     // W2 split
    pre_A2_kernel<<<4096, 256>>>(c2w);                                      // A2 split
    build_w3_kernel<<<1152, 256>>>(c1w);                                    // W3 split

    // GEMM1: h3 = split(relu(xcat*W1^T + b1)); logical K=3072
    hmma_kernel<256, 2><<<dim3(32, 4), 512, SM256>>>(
        (const unsigned short*)p_xcat3, (const unsigned short*)p_W13, b1,
        nullptr, (unsigned short*)p_h3, nullptr, 3072, 0, 0, 0, 0);

    // GEMM2 (batch z): vaT = vx*relu(h_z*W2_z^T + b2_z); logical K=1536
    hmma_kernel<256, 3><<<dim3(4, 4, 8), 512, SM256>>>(
        (const unsigned short*)p_h3, (const unsigned short*)p_W23, b2,
        (float*)p_vaT, nullptr, vx, 1536, 0,
        (size_t)1024 * 1024, (size_t)512 * 1024, 512);

    // conv operand, then conv GEMM: Y = X3*W3^T; logical K=4608
    build_x3_kernel<<<6144, 256>>>();
    hmma_kernel<256, 0><<<dim3(12, 32), 512, SM256>>>(
        (const unsigned short*)p_X3, (const unsigned short*)p_W3, nullptr,
        (float*)p_Y, nullptr, nullptr, 4608, 1536, 0, 0, 0);

    // pool -> p3
    pool_split_kernel<<<2048, 256>>>((const float*)p_Y, c1b);

    // GEMM3: out = relu(p*A2^T + c2b); logical K=6144
    hmma_kernel<128, 1><<<dim3(4, 8), 256, SM128>>>(
        (const unsigned short*)p_p3, (const unsigned short*)p_A23, c2b,
        out, nullptr, nullptr, 6144, 512, 0, 0, 0);
}

// round 8
// speedup vs baseline: 5.4120x; 1.2027x over previous
#include <cuda_runtime.h>
#include <cuda_fp16.h>
#include <cstdint>
#include <cstddef>

// B=1024, F=512, N=8 — heavy math on HMMA fp16 (fp32 accum) with split-precision.
// Splits stored DEDUPED as [hi|lo]. TERMS=3: logical [hi|lo|hi]x[hi|hi|lo] (err ~2^-22).
// TERMS=2: logical [hi|lo]x[hi|hi] = full-x times fp16-w (err ~2^-12) — used on the
// two largest GEMMs (conv, G1) to cut MMA-pipe work 29%.

#define LDK 40   // smem row stride in halves (80B, conflict-free ldmatrix)

// ---------------- static scratch (deduped splits) ----------------
__device__ unsigned short g_xcat3[(size_t)1024 * 2048];   // A-split of [vx|ax]
__device__ unsigned short g_W13[(size_t)4096 * 2048];     // B-split of W1
__device__ unsigned short g_h3[(size_t)8 * 1024 * 1024];  // [z][b][hi512|lo512]
__device__ unsigned short g_W23[(size_t)4096 * 1024];     // B-split of W2
__device__ float g_vaT[1024 * 8 * 512];                   // [B][i][F]
__device__ unsigned short g_X3[(size_t)8192 * 3072];      // conv A split (di-shifted)
__device__ unsigned short g_W3[(size_t)1536 * 3072];      // conv B split
__device__ float g_Y[(size_t)8192 * 1536];                // conv out
__device__ unsigned short g_p3[(size_t)1024 * 4096];      // pooled split
__device__ unsigned short g_A23[(size_t)512 * 4096];      // conv2-collapsed split

// ---------------- helpers ----------------
union Pack8 { unsigned short s[8]; uint4 v; };
__device__ __forceinline__ void split_hi_lo(float x, unsigned short& hi, unsigned short& lo) {
    __half h = __float2half_rn(x);
    float hf = __half2float(h);
    __half l = __float2half_rn(x - hf);
    hi = __half_as_ushort(h);
    lo = __half_as_ushort(l);
}
__device__ __forceinline__ uint32_t smem_u32(const void* p) {
    uint32_t a;
    asm("{ .reg .u64 t; cvta.to.shared.u64 t, %1; cvt.u32.u64 %0, t; }" : "=r"(a) : "l"(p));
    return a;
}
__device__ __forceinline__ void ldmatrix_x4(uint32_t& r0, uint32_t& r1, uint32_t& r2, uint32_t& r3,
                                            uint32_t addr) {
    asm volatile("ldmatrix.sync.aligned.m8n8.x4.shared.b16 {%0,%1,%2,%3}, [%4];"
                 : "=r"(r0), "=r"(r1), "=r"(r2), "=r"(r3) : "r"(addr));
}
__device__ __forceinline__ void mma_16816(float* c, const uint32_t* a, const uint32_t* b) {
    asm volatile("mma.sync.aligned.m16n8k16.row.col.f32.f16.f16.f32 "
                 "{%0,%1,%2,%3}, {%4,%5,%6,%7}, {%8,%9}, {%0,%1,%2,%3};"
                 : "+f"(c[0]), "+f"(c[1]), "+f"(c[2]), "+f"(c[3])
                 : "r"(a[0]), "r"(a[1]), "r"(a[2]), "r"(a[3]), "r"(b[0]), "r"(b[1]));
}
__device__ __forceinline__ void cp_async16(uint32_t dst, const void* src) {
    asm volatile("cp.async.cg.shared.global [%0], [%1], 16;" :: "r"(dst), "l"(src));
}
#define CP_COMMIT() asm volatile("cp.async.commit_group;" ::: "memory")
#define CP_WAIT0()  asm volatile("cp.async.wait_group 0;" ::: "memory")

// ---------------- operand builders ----------------
// [vx|ax] concat -> A-split [hi|lo], row stride 2048
__global__ void concat_split_kernel(const float* __restrict__ vx, const float* __restrict__ ax) {
    int idx = blockIdx.x * blockDim.x + threadIdx.x;  // 1024*128
    int kv = idx & 127, b = idx >> 7;
    const float* src = (kv < 64) ? (vx + (size_t)b * 512 + kv * 8)
                                 : (ax + (size_t)b * 512 + (kv - 64) * 8);
    float4 x0 = *(const float4*)src, x1 = *(const float4*)(src + 4);
    float vals[8] = {x0.x, x0.y, x0.z, x0.w, x1.x, x1.y, x1.z, x1.w};
    Pack8 hi, lo;
    #pragma unroll
    for (int j = 0; j < 8; j++) split_hi_lo(vals[j], hi.s[j], lo.s[j]);
    size_t e0 = (size_t)b * 2048 + kv * 8;
    *(uint4*)(g_xcat3 + e0)        = hi.v;
    *(uint4*)(g_xcat3 + e0 + 1024) = lo.v;
}

// B-split [hi|lo], row stride 2K
__global__ void split3B_kernel(const float* __restrict__ src, unsigned short* __restrict__ dst,
                               int Kv /* K/8 */, int K) {
    int idx = blockIdx.x * blockDim.x + threadIdx.x;  // R*Kv
    int kv = idx % Kv, r = idx / Kv;
    const float* s = src + (size_t)r * K + kv * 8;
    float4 x0 = *(const float4*)s, x1 = *(const float4*)(s + 4);
    float vals[8] = {x0.x, x0.y, x0.z, x0.w, x1.x, x1.y, x1.z, x1.w};
    Pack8 hi, lo;
    #pragma unroll
    for (int j = 0; j < 8; j++) split_hi_lo(vals[j], hi.s[j], lo.s[j]);
    size_t e0 = (size_t)r * 2 * K + kv * 8;
    *(uint4*)(dst + e0)     = hi.v;
    *(uint4*)(dst + e0 + K) = lo.v;
}

// conv2+mean collapse -> split, row stride 4096
__global__ void pre_A2_kernel(const float* __restrict__ w2) {
    int idx = blockIdx.x * blockDim.x + threadIdx.x;  // 512*512*4
    int q = idx & 3;
    int cf = idx >> 2;
    int f = cf & 511;
    int c = cf >> 9;
    int ip = q >> 1, jp = q & 1;
    const float* wb = w2 + (size_t)(c * 512 + f) * 9;
    float s = 0.f;
    #pragma unroll
    for (int i = 0; i < 2; i++)
        #pragma unroll
        for (int j = 0; j < 2; j++)
            s += wb[(ip - i + 1) * 3 + (jp - j + 1)];
    unsigned short hi, lo;
    split_hi_lo(0.25f * s, hi, lo);
    size_t e0 = (size_t)c * 4096 + f * 4 + q;
    g_A23[e0]        = hi;
    g_A23[e0 + 2048] = lo;
}

// conv A operand split: X3[r=(b,i)][di*512 + f], [hi|lo], row stride 3072
__global__ void build_x3_kernel() {
    int idx = blockIdx.x * blockDim.x + threadIdx.x;   // 8192*3*64
    int fg = idx & 63;
    int di = (idx >> 6) % 3;
    int r  = idx / 192;
    int b = r >> 3, i = r & 7;
    int src = i + di - 1;
    float vals[8];
    if (src >= 0 && src < 8) {
        const float4* p = (const float4*)(g_vaT + ((size_t)(b * 8 + src) * 512) + fg * 8);
        float4 x0 = p[0], x1 = p[1];
        vals[0] = x0.x; vals[1] = x0.y; vals[2] = x0.z; vals[3] = x0.w;
        vals[4] = x1.x; vals[5] = x1.y; vals[6] = x1.z; vals[7] = x1.w;
    } else {
        #pragma unroll
        for (int j = 0; j < 8; j++) vals[j] = 0.f;
    }
    Pack8 hi, lo;
    #pragma unroll
    for (int j = 0; j < 8; j++) split_hi_lo(vals[j], hi.s[j], lo.s[j]);
    size_t e0 = (size_t)r * 3072 + di * 512 + fg * 8;
    *(uint4*)(g_X3 + e0)        = hi.v;
    *(uint4*)(g_X3 + e0 + 1536) = lo.v;
}

// conv B operand split: W3[n=t*512+c][di*512+f], [hi|lo], row stride 3072
__global__ void build_w3_kernel(const float* __restrict__ c1w) {
    int idx = blockIdx.x * blockDim.x + threadIdx.x;   // 1536*3*64
    int fg = idx & 63;
    int di = (idx >> 6) % 3;
    int n  = idx / 192;
    int t = n >> 9, c = n & 511;
    Pack8 hi, lo;
    #pragma unroll
    for (int j = 0; j < 8; j++) {
        int f = fg * 8 + j;
        size_t base = ((size_t)(c * 512 + f) * 3 + di) * 3;
        float w;
        if (t == 0)      w = c1w[base] + c1w[base + 1] + c1w[base + 2];
        else if (t == 1) w = c1w[base];
        else             w = c1w[base + 2];
        split_hi_lo(w, hi.s[j], lo.s[j]);
    }
    size_t e0 = (size_t)n * 3072 + di * 512 + fg * 8;
    *(uint4*)(g_W3 + e0)        = hi.v;
    *(uint4*)(g_W3 + e0 + 1536) = lo.v;
}

// ---------------- unified HMMA GEMM ----------------
// Logical K = Ks. Stored row stride: TERMS==3 -> 2Ks/3 ([hi|lo] both used in 3-term
// pairing), TERMS==2 -> Ks for A ([hi|lo] all used), B reads only its hi half.
// TERMS==3: nb=NIT/3, A blocks [hi|lo|hi] (kA = k<2nb?k:k-2nb), B [hi|hi|lo] (kB = k<nb?k:k-nb)
// TERMS==2: nb=NIT/2, A blocks [hi|lo]   (kA = k),              B [hi|hi]    (kB = k<nb?k:k-nb)
// MODE 0: outF = acc (conv->Y)   MODE 1: relu(acc+bias) (G3->out)
// MODE 2: h3 deduped split store (G1)   MODE 3: vaT epilogue (G2)
template <int TM, int MODE, int TERMS>
__global__ void __launch_bounds__((TM == 256) ? 512 : 256, (TM == 256) ? 1 : 2)
hmma_kernel(const unsigned short* __restrict__ A, const unsigned short* __restrict__ Bm,
            const float* __restrict__ bias, float* __restrict__ outF,
            unsigned short* __restrict__ outH, const float* __restrict__ vx,
            int Ks, int ldc, size_t batchA, size_t batchB, int batchBias)
{
    constexpr int THREADS = (TM == 256) ? 512 : 256;
    constexpr int ROWS = TM + 128;
    constexpr int CH = ROWS * 4 / THREADS;
    constexpr int WMC = TM / 64;
    constexpr int ABUF = TM * LDK;
    constexpr int BBUF = 128 * LDK;

    extern __shared__ __align__(16) unsigned short smem[];
    unsigned short* sA = smem;                 // [2][ABUF]
    unsigned short* sB = smem + 2 * ABUF;      // [2][BBUF]

    const int tid = threadIdx.x;
    const int wid = tid >> 5, lane = tid & 31;
    const int m0 = blockIdx.y * TM;
    const int n0 = blockIdx.x * 128;
    const int z  = blockIdx.z;
    const int wm = (wid % WMC) * 64;
    const int wn = (wid / WMC) * 32;

    const int SK = (TERMS == 3) ? (2 * Ks) / 3 : Ks;   // stored row stride
    const int NIT = Ks / 32;
    const int nb = (TERMS == 3) ? NIT / 3 : NIT / 2;

    A  += (size_t)z * batchA;
    Bm += (size_t)z * batchB;
    if (MODE >= 1) bias += (size_t)z * batchBias;

    // staging maps (cp.async)
    const unsigned short* gp[CH];
    uint32_t sdA[CH];
    bool isA_[CH];
    #pragma unroll
    for (int t = 0; t < CH; t++) {
        int id = tid + t * THREADS;
        int r = id >> 2, q = id & 3;
        if (r < TM) {
            gp[t] = A + (size_t)(m0 + r) * SK + q * 8;
            sdA[t] = smem_u32(sA + r * LDK + q * 8);
            isA_[t] = true;
        } else {
            gp[t] = Bm + (size_t)(n0 + r - TM) * SK + q * 8;
            sdA[t] = smem_u32(sB + (r - TM) * LDK + q * 8);
            isA_[t] = false;
        }
    }

    float acc[4][4][4];
    #pragma unroll
    for (int i = 0; i < 4; i++)
        #pragma unroll
        for (int j = 0; j < 4; j++)
            #pragma unroll
            for (int q = 0; q < 4; q++) acc[i][j][q] = 0.f;

    const uint32_t sA_base = smem_u32(sA);
    const uint32_t sB_base = smem_u32(sB);
    const int aRow = wm + (lane & 15);
    const int aKof = (lane >> 4) * 8;
    const int bRow = wn + ((lane & 7) | ((lane >> 4) << 3));
    const int bKof = ((lane >> 3) & 1) * 8;

    // stage logical chunk k into buffer buf
    auto stage = [&](int k, int buf) {
        int kA = (TERMS == 3) ? ((k < 2 * nb) ? k : k - 2 * nb) : k;
        int kB = (k < nb) ? k : k - nb;
        #pragma unroll
        for (int t = 0; t < CH; t++) {
            const unsigned short* src = gp[t] + (size_t)(isA_[t] ? kA : kB) * 32;
            uint32_t dst = sdA[t] + (uint32_t)buf * (isA_[t] ? ABUF : BBUF) * 2;
            cp_async16(dst, src);
        }
        CP_COMMIT();
    };

    stage(0, 0);
    CP_WAIT0();
    __syncthreads();

    for (int it = 0; it < NIT; it++) {
        const int cur = it & 1;
        const bool more = (it + 1) < NIT;
        if (more) stage(it + 1, cur ^ 1);

        const uint32_t aBuf = sA_base + cur * (ABUF * 2);
        const uint32_t bBuf = sB_base + cur * (BBUF * 2);
        #pragma unroll
        for (int ks = 0; ks < 32; ks += 16) {
            uint32_t af[4][4], bf[4][2];
            #pragma unroll
            for (int mt = 0; mt < 4; mt++)
                ldmatrix_x4(af[mt][0], af[mt][1], af[mt][2], af[mt][3],
                            aBuf + (uint32_t)(((aRow + mt * 16) * LDK + ks + aKof) * 2));
            #pragma unroll
            for (int np = 0; np < 2; np++)
                ldmatrix_x4(bf[np * 2][0], bf[np * 2][1], bf[np * 2 + 1][0], bf[np * 2 + 1][1],
                            bBuf + (uint32_t)(((bRow + np * 16) * LDK + ks + bKof) * 2));
            #pragma unroll
            for (int mt = 0; mt < 4; mt++)
                #pragma unroll
                for (int nt = 0; nt < 4; nt++)
                    mma_16816(acc[mt][nt], af[mt], bf[nt]);
        }
        if (more) CP_WAIT0();
        __syncthreads();
    }

    // epilogue
    const int erow = lane >> 2;
    const int ecol = (lane & 3) * 2;
    #pragma unroll
    for (int mt = 0; mt < 4; mt++) {
        #pragma unroll
        for (int nt = 0; nt < 4; nt++) {
            const int r0 = m0 + wm + mt * 16 + erow;
            const int c  = n0 + wn + nt * 8 + ecol;
            const float* v = acc[mt][nt];
            if (MODE == 0) {
                *(float2*)&outF[(size_t)r0 * ldc + c] = make_float2(v[0], v[1]);
                *(float2*)&outF[(size_t)(r0 + 8) * ldc + c] = make_float2(v[2], v[3]);
            } else if (MODE == 1) {
                float b0 = bias[c], b1 = bias[c + 1];
                *(float2*)&outF[(size_t)r0 * ldc + c] =
                    make_float2(fmaxf(v[0] + b0, 0.f), fmaxf(v[1] + b1, 0.f));
                *(float2*)&outF[(size_t)(r0 + 8) * ldc + c] =
                    make_float2(fmaxf(v[2] + b0, 0.f), fmaxf(v[3] + b1, 0.f));
            } else if (MODE == 2) {
                float b0 = bias[c], b1 = bias[c + 1];
                int zz = c >> 9, f = c & 511;
                #pragma unroll
                for (int hr = 0; hr < 2; hr++) {
                    float y0 = fmaxf(v[hr * 2] + b0, 0.f);
                    float y1 = fmaxf(v[hr * 2 + 1] + b1, 0.f);
                    unsigned short h0, l0, h1, l1;
                    split_hi_lo(y0, h0, l0);
                    split_hi_lo(y1, h1, l1);
                    uint32_t hip = (uint32_t)h0 | ((uint32_t)h1 << 16);
                    uint32_t lop = (uint32_t)l0 | ((uint32_t)l1 << 16);
                    size_t base = ((size_t)zz * 1024 + (r0 + hr * 8)) * 1024 + f;
                    *(uint32_t*)&outH[base]       = hip;
                    *(uint32_t*)&outH[base + 512] = lop;
                }
            } else {  // MODE 3
                float b0 = bias[c], b1 = bias[c + 1];
                #pragma unroll
                for (int hr = 0; hr < 2; hr++) {
                    int r = r0 + hr * 8;
                    float s0 = vx[(size_t)r * 512 + c];
                    float s1 = vx[(size_t)r * 512 + c + 1];
                    float y0 = s0 * fmaxf(v[hr * 2] + b0, 0.f);
                    float y1 = s1 * fmaxf(v[hr * 2 + 1] + b1, 0.f);
                    *(float2*)&outF[((size_t)r * 8 + z) * 512 + c] = make_float2(y0, y1);
                }
            }
        }
    }
}

// ---------------- pool: Y -> p3 (deduped split) ----------------
__global__ void pool_split_kernel(const float* __restrict__ Y, const float* __restrict__ c1b) {
    int idx = blockIdx.x * blockDim.x + threadIdx.x;   // 1024*512
    int c = idx & 511, b = idx >> 9;
    float bias = c1b[c];
    float m00 = -1e30f, m01 = -1e30f, m10 = -1e30f, m11 = -1e30f;
    #pragma unroll
    for (int i = 0; i < 8; i++) {
        size_t base = (size_t)(b * 8 + i) * 1536;
        float yM = Y[base + c];
        float yB = Y[base + 512 + c];
        float yC = Y[base + 1024 + c];
        float vL = fmaxf(yM - yB, yM);
        float vR = fmaxf(yM - yC, yM);
        if (i < 4) { m00 = fmaxf(m00, vL); m01 = fmaxf(m01, vR); }
        else       { m10 = fmaxf(m10, vL); m11 = fmaxf(m11, vR); }
    }
    float p[4] = {m00 + bias, m01 + bias, m10 + bias, m11 + bias};
    ushort4 hi, lo;
    split_hi_lo(p[0], hi.x, lo.x);
    split_hi_lo(p[1], hi.y, lo.y);
    split_hi_lo(p[2], hi.z, lo.z);
    split_hi_lo(p[3], hi.w, lo.w);
    size_t e0 = (size_t)b * 4096 + c * 4;
    *(ushort4*)(g_p3 + e0)        = hi;
    *(ushort4*)(g_p3 + e0 + 2048) = lo;
}

// ---------------- launch ----------------
extern "C" void kernel_launch(void* const* d_in, const int* in_sizes, int n_in,
                              void* d_out, int out_size) {
    (void)in_sizes; (void)n_in; (void)out_size;
    const float* vx  = (const float*)d_in[0];
    const float* ax  = (const float*)d_in[1];
    const float* W1  = (const float*)d_in[2];
    const float* b1  = (const float*)d_in[3];
    const float* W2  = (const float*)d_in[4];
    const float* b2  = (const float*)d_in[5];
    const float* c1w = (const float*)d_in[6];
    const float* c1b = (const float*)d_in[7];
    const float* c2w = (const float*)d_in[8];
    const float* c2b = (const float*)d_in[9];
    float* out = (float*)d_out;

    void *p_xcat3, *p_W13, *p_h3, *p_W23, *p_X3, *p_W3, *p_Y, *p_p3, *p_A23, *p_vaT;
    cudaGetSymbolAddress(&p_xcat3, g_xcat3);
    cudaGetSymbolAddress(&p_W13,   g_W13);
    cudaGetSymbolAddress(&p_h3,    g_h3);
    cudaGetSymbolAddress(&p_W23,   g_W23);
    cudaGetSymbolAddress(&p_X3,    g_X3);
    cudaGetSymbolAddress(&p_W3,    g_W3);
    cudaGetSymbolAddress(&p_Y,     g_Y);
    cudaGetSymbolAddress(&p_p3,    g_p3);
    cudaGetSymbolAddress(&p_A23,   g_A23);
    cudaGetSymbolAddress(&p_vaT,   g_vaT);

    const int SM256 = (2 * 256 + 2 * 128) * LDK * 2;  // 61440
    const int SM128 = (2 * 128 + 2 * 128) * LDK * 2;  // 40960
    cudaFuncSetAttribute((const void*)hmma_kernel<256, 0, 2>, cudaFuncAttributeMaxDynamicSharedMemorySize, SM256);
    cudaFuncSetAttribute((const void*)hmma_kernel<256, 2, 2>, cudaFuncAttributeMaxDynamicSharedMemorySize, SM256);
    cudaFuncSetAttribute((const void*)hmma_kernel<256, 3, 3>, cudaFuncAttributeMaxDynamicSharedMemorySize, SM256);
    cudaFuncSetAttribute((const void*)hmma_kernel<128, 1, 3>, cudaFuncAttributeMaxDynamicSharedMemorySize, SM128);

    // operand builders
    concat_split_kernel<<<512, 256>>>(vx, ax);                              // xcat3
    split3B_kernel<<<2048, 256>>>(W1, (unsigned short*)p_W13, 128, 1024);   // W1 split
    split3B_kernel<<<1024, 256>>>(W2, (unsigned short*)p_W23, 64, 512);     // W2 split
    pre_A2_kernel<<<4096, 256>>>(c2w);                                      // A2 split
    build_w3_kernel<<<1152, 256>>>(c1w);                                    // W3 split

    // GEMM1 (2-term): h3 = split(relu(xcat*W1^T + b1)); logical K=2048
    hmma_kernel<256, 2, 2><<<dim3(32, 4), 512, SM256>>>(
        (const unsigned short*)p_xcat3, (const unsigned short*)p_W13, b1,
        nullptr, (unsigned short*)p_h3, nullptr, 2048, 0, 0, 0, 0);

    // GEMM2 (3-term, batch z): vaT = vx*relu(h_z*W2_z^T + b2_z); logical K=1536
    hmma_kernel<256, 3, 3><<<dim3(4, 4, 8), 512, SM256>>>(
        (const unsigned short*)p_h3, (const unsigned short*)p_W23, b2,
        (float*)p_vaT, nullptr, vx, 1536, 0,
        (size_t)1024 * 1024, (size_t)512 * 1024, 512);

    // conv operand, then conv GEMM (2-term): Y = X3*W3^T; logical K=3072
    build_x3_kernel<<<6144, 256>>>();
    hmma_kernel<256, 0, 2><<<dim3(12, 32), 512, SM256>>>(
        (const unsigned short*)p_X3, (const unsigned short*)p_W3, nullptr,
        (float*)p_Y, nullptr, nullptr, 3072, 1536, 0, 0, 0);

    // pool -> p3
    pool_split_kernel<<<2048, 256>>>((const float*)p_Y, c1b);

    // GEMM3 (3-term): out = relu(p*A2^T + c2b); logical K=6144
    hmma_kernel<128, 1, 3><<<dim3(4, 8), 256, SM128>>>(
        (const unsigned short*)p_p3, (const unsigned short*)p_A23, c2b,
        out, nullptr, nullptr, 6144, 512, 0, 0, 0);
}